// round 2
// baseline (speedup 1.0000x reference)
#include <cuda_runtime.h>
#include <cstdint>

// Problem constants
#define BB    8
#define NTOK  16384
#define KCOMP 64
#define CGRP  256       // N / K
#define CDIM  8192      // C_OUT == C_IN
#define IPTS  512       // points per group = K * 8

#define DENS_PITCH 520  // 512 + 8 padding -> conflict-free smem
#define SMEM_FLOATS (KCOMP*DENS_PITCH + 2*IPTS + 5*KCOMP)
#define SMEM_BYTES  (SMEM_FLOATS * 4)

// ---------------------------------------------------------------------------
// threefry2x32 (20 rounds), usable on host and device
// ---------------------------------------------------------------------------
__host__ __device__ __forceinline__
void threefry2x32(uint32_t k0, uint32_t k1, uint32_t x0, uint32_t x1,
                  uint32_t& y0, uint32_t& y1)
{
    uint32_t ks2 = k0 ^ k1 ^ 0x1BD11BDAu;
#define TF_RND(r) { x0 += x1; x1 = (x1 << (r)) | (x1 >> (32 - (r))); x1 ^= x0; }
    x0 += k0; x1 += k1;
    TF_RND(13) TF_RND(15) TF_RND(26) TF_RND(6)
    x0 += k1;  x1 += ks2 + 1u;
    TF_RND(17) TF_RND(29) TF_RND(16) TF_RND(24)
    x0 += ks2; x1 += k0 + 2u;
    TF_RND(13) TF_RND(15) TF_RND(26) TF_RND(6)
    x0 += k0;  x1 += k1 + 3u;
    TF_RND(17) TF_RND(29) TF_RND(16) TF_RND(24)
    x0 += k1;  x1 += ks2 + 4u;
    TF_RND(13) TF_RND(15) TF_RND(26) TF_RND(6)
    x0 += ks2; x1 += k0 + 5u;
#undef TF_RND
    y0 = x0; y1 = x1;
}

// jax partitionable random_bits (32-bit) at flat index f (< 2^32):
// counter = (hi=0, lo=f); bits = word0 ^ word1.
__device__ __forceinline__
float jax_uniform_at(uint32_t k0, uint32_t k1, uint32_t f)
{
    uint32_t y0, y1;
    threefry2x32(k0, k1, 0u, f, y0, y1);
    uint32_t bits = y0 ^ y1;
    return __uint_as_float((bits >> 9) | 0x3F800000u) - 1.0f;
}

// ---------------------------------------------------------------------------
// Kernel 1: y = bias (broadcast over batch)
// ---------------------------------------------------------------------------
__global__ void init_out_kernel(float* __restrict__ y, const float* __restrict__ bias)
{
    int o = blockIdx.x * blockDim.x + threadIdx.x;
    if (o < BB * CDIM) y[o] = bias[o & (CDIM - 1)];
}

// ---------------------------------------------------------------------------
// Kernel 2: one CTA per (b, c) group
// ---------------------------------------------------------------------------
__global__ void __launch_bounds__(512, 1)
sparse_main_kernel(const float* __restrict__ x,
                   const float* __restrict__ means,
                   const float* __restrict__ sigmas,
                   const float* __restrict__ values,
                   float* __restrict__ y,
                   uint32_t kg0, uint32_t kg1, uint32_t kl0, uint32_t kl1)
{
    extern __shared__ float sm[];
    float* dens = sm;                              // [64][520]
    float* p0s  = dens + KCOMP * DENS_PITCH;       // [512]
    float* p1s  = p0s + IPTS;                      // [512]
    float* mm0  = p1s + IPTS;                      // [64]
    float* mm1  = mm0 + KCOMP;
    float* qq0  = mm1 + KCOMP;
    float* qq1  = qq0 + KCOMP;
    float* vno  = qq1 + KCOMP;                     // values[k] / colsum[k]

    const int grp = blockIdx.x;          // b*256 + c
    const int b   = grp >> 8;
    const int c   = grp & 255;
    const int tid = threadIdx.x;

    const float OME = (float)(1.0 - 1e-6);   // (1 - EPS) rounded to f32, same as jax

    // ---- load component params ----
    if (tid < KCOMP) {
        int k = tid;
        size_t base = ((size_t)b * NTOK + (size_t)c * KCOMP + k);
        mm0[k] = means[base * 2 + 0];
        mm1[k] = means[base * 2 + 1];
        qq0[k] = 1.0f / (1e-6f + sigmas[base * 2 + 0]);
        qq1[k] = 1.0f / (1e-6f + sigmas[base * 2 + 1]);
    }
    __syncthreads();

    // ---- generate 512 integer points (as floats) ----
    {
        int k = tid >> 3;
        int j = tid & 7;
        float m0 = mm0[k], m1 = mm1[k];
        float r0, r1;
        if (j < 4) {
            // combos from itertools.product([True,False],2): True -> floor
            r0 = (j < 2)        ? floorf(m0) : ceilf(m0);
            r1 = ((j & 1) == 0) ? floorf(m1) : ceilf(m1);
        } else {
            int g = j & 1;  // j=4,6 -> g=0 ; j=5,7 -> g=1
            uint32_t fbase = (uint32_t)(((grp * KCOMP + k) * 2 + g) * 2);
            if (j < 6) {
                // gints: floor(u*(1-eps) * 8192)  (x8192 is exact)
                float u0 = jax_uniform_at(kg0, kg1, fbase + 0);
                float u1 = jax_uniform_at(kg0, kg1, fbase + 1);
                r0 = floorf((u0 * OME) * 8192.0f);
                r1 = floorf((u1 * OME) * 8192.0f);
            } else {
                // lints: floor(u*(1-eps)*16 + lower)  (x16 exact, single rounding)
                float u0 = jax_uniform_at(kl0, kl1, fbase + 0);
                float u1 = jax_uniform_at(kl0, kl1, fbase + 1);
                float mr0 = rintf(m0), mr1 = rintf(m1);
                float lo0 = mr0 - 8.0f;
                if (lo0 < 0.0f) lo0 = 0.0f;
                if (mr0 + 8.0f > 8192.0f) lo0 = 8176.0f;
                float lo1 = mr1 - 8.0f;
                if (lo1 < 0.0f) lo1 = 0.0f;
                if (mr1 + 8.0f > 8192.0f) lo1 = 8176.0f;
                r0 = floorf((u0 * OME) * 16.0f + lo0);
                r1 = floorf((u1 * OME) * 16.0f + lo1);
            }
        }
        r0 = fminf(fmaxf(r0, 0.0f), 8191.0f);
        r1 = fminf(fmaxf(r1, 0.0f), 8191.0f);
        p0s[tid] = r0;
        p1s[tid] = r1;
    }
    __syncthreads();

    // ---- density pass: dens[k][i] = max(exp(-0.5*((p-m)^2 . q)), eps), colsum ----
    {
        int kk = tid >> 3;
        int io = tid & 7;
        float m0 = mm0[kk], m1 = mm1[kk], q0 = qq0[kk], q1 = qq1[kk];
        float* drow = dens + kk * DENS_PITCH;
        float acc = 0.0f;
#pragma unroll 4
        for (int s = 0; s < 64; s++) {
            int i = io + (s << 3);
            float d0 = p0s[i] - m0;
            float d1 = p1s[i] - m1;
            float t  = d0 * d0 * q0 + d1 * d1 * q1;
            float e  = __expf(-0.5f * t);
            e = fmaxf(e, 1e-6f);
            drow[i] = e;
            acc += e;
        }
        // reduce over the 8 lanes owning the same k (lanes are segment-aligned)
        acc += __shfl_down_sync(0xFFFFFFFFu, acc, 4);
        acc += __shfl_down_sync(0xFFFFFFFFu, acc, 2);
        acc += __shfl_down_sync(0xFFFFFFFFu, acc, 1);
        if (io == 0) {
            float v = values[(size_t)b * NTOK + (size_t)c * KCOMP + kk];
            vno[kk] = v / acc;
        }
    }
    __syncthreads();

    // ---- weights + gather + scatter ----
    {
        float w = 0.0f;
#pragma unroll 8
        for (int k = 0; k < KCOMP; k++) {
            w += dens[k * DENS_PITCH + tid] * vno[k];
        }
        int i0 = (int)p0s[tid];
        int i1 = (int)p1s[tid];
        float g = x[(size_t)b * CDIM + i1];
        atomicAdd(&y[(size_t)b * CDIM + i0], w * g);
    }
}

// ---------------------------------------------------------------------------
// Launch
// ---------------------------------------------------------------------------
extern "C" void kernel_launch(void* const* d_in, const int* in_sizes, int n_in,
                              void* d_out, int out_size)
{
    const float* x      = (const float*)d_in[0];
    const float* means  = (const float*)d_in[1];
    const float* sigmas = (const float*)d_in[2];
    const float* values = (const float*)d_in[3];
    const float* bias   = (const float*)d_in[4];
    float* y = (float*)d_out;

    // jax_threefry_partitionable split (fold-like):
    // kg, kl = split(key(42)):  key i = both output words of threefry(key, (0, i))
    uint32_t kg0, kg1, kl0, kl1;
    threefry2x32(0u, 42u, 0u, 0u, kg0, kg1);
    threefry2x32(0u, 42u, 0u, 1u, kl0, kl1);

    init_out_kernel<<<(BB * CDIM + 255) / 256, 256>>>(y, bias);

    cudaFuncSetAttribute(sparse_main_kernel,
                         cudaFuncAttributeMaxDynamicSharedMemorySize, SMEM_BYTES);
    sparse_main_kernel<<<BB * CGRP, 512, SMEM_BYTES>>>(
        x, means, sigmas, values, y, kg0, kg1, kl0, kl1);
}

// round 3
// speedup vs baseline: 1.4813x; 1.4813x over previous
#include <cuda_runtime.h>
#include <cuda_fp16.h>
#include <cstdint>

// Problem constants
#define BB    8
#define NTOK  16384
#define KCOMP 64
#define CGRP  256       // N / K
#define CDIM  8192      // C_OUT == C_IN
#define IPTS  512       // points per group = K * 8

#define DENS_PITCH 528  // halfs per row: 512 + 16 pad
#define DENS_HALFS (KCOMP * DENS_PITCH)            // 33792 halfs = 67584 B
#define DENS_FLOAT_OFF (DENS_HALFS / 2)            // offset in floats
#define SMEM_FLOATS (DENS_FLOAT_OFF + 2*IPTS + 5*KCOMP)
#define SMEM_BYTES  (SMEM_FLOATS * 4)

// ---------------------------------------------------------------------------
// threefry2x32 (20 rounds), usable on host and device
// ---------------------------------------------------------------------------
__host__ __device__ __forceinline__
void threefry2x32(uint32_t k0, uint32_t k1, uint32_t x0, uint32_t x1,
                  uint32_t& y0, uint32_t& y1)
{
    uint32_t ks2 = k0 ^ k1 ^ 0x1BD11BDAu;
#define TF_RND(r) { x0 += x1; x1 = (x1 << (r)) | (x1 >> (32 - (r))); x1 ^= x0; }
    x0 += k0; x1 += k1;
    TF_RND(13) TF_RND(15) TF_RND(26) TF_RND(6)
    x0 += k1;  x1 += ks2 + 1u;
    TF_RND(17) TF_RND(29) TF_RND(16) TF_RND(24)
    x0 += ks2; x1 += k0 + 2u;
    TF_RND(13) TF_RND(15) TF_RND(26) TF_RND(6)
    x0 += k0;  x1 += k1 + 3u;
    TF_RND(17) TF_RND(29) TF_RND(16) TF_RND(24)
    x0 += k1;  x1 += ks2 + 4u;
    TF_RND(13) TF_RND(15) TF_RND(26) TF_RND(6)
    x0 += ks2; x1 += k0 + 5u;
#undef TF_RND
    y0 = x0; y1 = x1;
}

// jax partitionable random_bits (32-bit) at flat index f (< 2^32):
// counter = (hi=0, lo=f); bits = word0 ^ word1.
__device__ __forceinline__
float jax_uniform_at(uint32_t k0, uint32_t k1, uint32_t f)
{
    uint32_t y0, y1;
    threefry2x32(k0, k1, 0u, f, y0, y1);
    uint32_t bits = y0 ^ y1;
    return __uint_as_float((bits >> 9) | 0x3F800000u) - 1.0f;
}

// ---------------------------------------------------------------------------
// Kernel 1: y = bias (broadcast over batch)
// ---------------------------------------------------------------------------
__global__ void init_out_kernel(float* __restrict__ y, const float* __restrict__ bias)
{
    int o = blockIdx.x * blockDim.x + threadIdx.x;
    if (o < BB * CDIM) y[o] = bias[o & (CDIM - 1)];
}

// ---------------------------------------------------------------------------
// Kernel 2: one CTA per (b, c) group; fp16 density matrix -> 3 CTAs/SM
// ---------------------------------------------------------------------------
__global__ void __launch_bounds__(512, 3)
sparse_main_kernel(const float* __restrict__ x,
                   const float* __restrict__ means,
                   const float* __restrict__ sigmas,
                   const float* __restrict__ values,
                   float* __restrict__ y,
                   uint32_t kg0, uint32_t kg1, uint32_t kl0, uint32_t kl1)
{
    extern __shared__ float sm[];
    __half* dens = (__half*)sm;                    // [64][528] halfs, e * 1024
    float* p0s  = sm + DENS_FLOAT_OFF;             // [512]
    float* p1s  = p0s + IPTS;                      // [512]
    float* mm0  = p1s + IPTS;                      // [64]
    float* mm1  = mm0 + KCOMP;
    float* qq0  = mm1 + KCOMP;                     // -0.5*log2(e) / (eps + sigma)
    float* qq1  = qq0 + KCOMP;
    float* vno  = qq1 + KCOMP;                     // values[k] / (colsum[k] * 1024)

    const int grp = blockIdx.x;          // b*256 + c
    const int b   = grp >> 8;
    const int c   = grp & 255;
    const int tid = threadIdx.x;

    const float OME = (float)(1.0 - 1e-6);   // (1 - EPS) rounded to f32, same as jax
    const float NHL2E = -0.72134752044448170f; // -0.5 * log2(e)

    // ---- load component params ----
    if (tid < KCOMP) {
        int k = tid;
        size_t base = ((size_t)b * NTOK + (size_t)c * KCOMP + k);
        mm0[k] = means[base * 2 + 0];
        mm1[k] = means[base * 2 + 1];
        qq0[k] = NHL2E / (1e-6f + sigmas[base * 2 + 0]);
        qq1[k] = NHL2E / (1e-6f + sigmas[base * 2 + 1]);
    }
    __syncthreads();

    // ---- generate 512 integer points (as floats) ----
    {
        int k = tid >> 3;
        int j = tid & 7;
        float m0 = mm0[k], m1 = mm1[k];
        float r0, r1;
        if (j < 4) {
            // combos from itertools.product([True,False],2): True -> floor
            r0 = (j < 2)        ? floorf(m0) : ceilf(m0);
            r1 = ((j & 1) == 0) ? floorf(m1) : ceilf(m1);
        } else {
            int g = j & 1;  // j=4,6 -> g=0 ; j=5,7 -> g=1
            uint32_t fbase = (uint32_t)(((grp * KCOMP + k) * 2 + g) * 2);
            if (j < 6) {
                // gints: floor(u*(1-eps) * 8192)  (x8192 is exact)
                float u0 = jax_uniform_at(kg0, kg1, fbase + 0);
                float u1 = jax_uniform_at(kg0, kg1, fbase + 1);
                r0 = floorf((u0 * OME) * 8192.0f);
                r1 = floorf((u1 * OME) * 8192.0f);
            } else {
                // lints: floor(u*(1-eps)*16 + lower)  (x16 exact, single rounding)
                float u0 = jax_uniform_at(kl0, kl1, fbase + 0);
                float u1 = jax_uniform_at(kl0, kl1, fbase + 1);
                float mr0 = rintf(m0), mr1 = rintf(m1);
                float lo0 = mr0 - 8.0f;
                if (lo0 < 0.0f) lo0 = 0.0f;
                if (mr0 + 8.0f > 8192.0f) lo0 = 8176.0f;
                float lo1 = mr1 - 8.0f;
                if (lo1 < 0.0f) lo1 = 0.0f;
                if (mr1 + 8.0f > 8192.0f) lo1 = 8176.0f;
                r0 = floorf((u0 * OME) * 16.0f + lo0);
                r1 = floorf((u1 * OME) * 16.0f + lo1);
            }
        }
        r0 = fminf(fmaxf(r0, 0.0f), 8191.0f);
        r1 = fminf(fmaxf(r1, 0.0f), 8191.0f);
        p0s[tid] = r0;
        p1s[tid] = r1;
    }
    __syncthreads();

    // ---- density pass: dens[k][i] = 1024*max(exp(-0.5*((p-m)^2 . q)), eps) ----
    {
        int kk = tid >> 3;
        int io = tid & 7;
        float m0 = mm0[kk], m1 = mm1[kk], q0 = qq0[kk], q1 = qq1[kk];
        __half* drow = dens + kk * DENS_PITCH;
        float acc = 0.0f;
#pragma unroll 4
        for (int s = 0; s < 64; s++) {
            int i = io + (s << 3);
            float d0 = p0s[i] - m0;
            float d1 = p1s[i] - m1;
            float t  = d0 * d0 * q0 + d1 * d1 * q1;   // already includes -0.5*log2e
            float e  = exp2f(t);
            e = fmaxf(e, 1e-6f);
            drow[i] = __float2half_rn(e * 1024.0f);   // exact scale; fp16-normal range
            acc += e;                                  // colsum in fp32, unrounded
        }
        // reduce over the 8 lanes owning the same k (lanes are segment-aligned)
        acc += __shfl_down_sync(0xFFFFFFFFu, acc, 4);
        acc += __shfl_down_sync(0xFFFFFFFFu, acc, 2);
        acc += __shfl_down_sync(0xFFFFFFFFu, acc, 1);
        if (io == 0) {
            float v = values[(size_t)b * NTOK + (size_t)c * KCOMP + kk];
            vno[kk] = (v / acc) * (1.0f / 1024.0f);   // fold out the fp16 scale
        }
    }
    __syncthreads();

    // ---- weights + gather + scatter ----
    {
        float w = 0.0f;
#pragma unroll 16
        for (int k = 0; k < KCOMP; k++) {
            w += __half2float(dens[k * DENS_PITCH + tid]) * vno[k];
        }
        int i0 = (int)p0s[tid];
        int i1 = (int)p1s[tid];
        float g = x[(size_t)b * CDIM + i1];
        atomicAdd(&y[(size_t)b * CDIM + i0], w * g);
    }
}

// ---------------------------------------------------------------------------
// Launch
// ---------------------------------------------------------------------------
extern "C" void kernel_launch(void* const* d_in, const int* in_sizes, int n_in,
                              void* d_out, int out_size)
{
    const float* x      = (const float*)d_in[0];
    const float* means  = (const float*)d_in[1];
    const float* sigmas = (const float*)d_in[2];
    const float* values = (const float*)d_in[3];
    const float* bias   = (const float*)d_in[4];
    float* y = (float*)d_out;

    // jax_threefry_partitionable split (fold-like):
    // kg, kl = split(key(42)):  key i = both output words of threefry(key, (0, i))
    uint32_t kg0, kg1, kl0, kl1;
    threefry2x32(0u, 42u, 0u, 0u, kg0, kg1);
    threefry2x32(0u, 42u, 0u, 1u, kl0, kl1);

    init_out_kernel<<<(BB * CDIM + 255) / 256, 256>>>(y, bias);

    cudaFuncSetAttribute(sparse_main_kernel,
                         cudaFuncAttributeMaxDynamicSharedMemorySize, SMEM_BYTES);
    sparse_main_kernel<<<BB * CGRP, 512, SMEM_BYTES>>>(
        x, means, sigmas, values, y, kg0, kg1, kl0, kl1);
}

// round 4
// speedup vs baseline: 1.6397x; 1.1070x over previous
#include <cuda_runtime.h>
#include <cuda_fp16.h>
#include <cstdint>

// Problem constants
#define BB    8
#define NTOK  16384
#define KCOMP 64
#define CGRP  256       // N / K
#define CDIM  8192      // C_OUT == C_IN
#define IPTS  512       // points per group = K * 8

// Row layout: 64 halfs (dens, e*1024) + float p0 + float p1 = 136 bytes
#define ROW_BYTES 136
#define ROWS_BYTES (IPTS * ROW_BYTES)              // 69632
#define AUX_FLOATS (5 * KCOMP)                     // vno, mm0, mm1, qq0, qq1
#define SMEM_BYTES (ROWS_BYTES + AUX_FLOATS * 4)   // 70912

// ---------------------------------------------------------------------------
// threefry2x32 (20 rounds), usable on host and device
// ---------------------------------------------------------------------------
__host__ __device__ __forceinline__
void threefry2x32(uint32_t k0, uint32_t k1, uint32_t x0, uint32_t x1,
                  uint32_t& y0, uint32_t& y1)
{
    uint32_t ks2 = k0 ^ k1 ^ 0x1BD11BDAu;
#define TF_RND(r) { x0 += x1; x1 = (x1 << (r)) | (x1 >> (32 - (r))); x1 ^= x0; }
    x0 += k0; x1 += k1;
    TF_RND(13) TF_RND(15) TF_RND(26) TF_RND(6)
    x0 += k1;  x1 += ks2 + 1u;
    TF_RND(17) TF_RND(29) TF_RND(16) TF_RND(24)
    x0 += ks2; x1 += k0 + 2u;
    TF_RND(13) TF_RND(15) TF_RND(26) TF_RND(6)
    x0 += k0;  x1 += k1 + 3u;
    TF_RND(17) TF_RND(29) TF_RND(16) TF_RND(24)
    x0 += k1;  x1 += ks2 + 4u;
    TF_RND(13) TF_RND(15) TF_RND(26) TF_RND(6)
    x0 += ks2; x1 += k0 + 5u;
#undef TF_RND
    y0 = x0; y1 = x1;
}

// jax partitionable random_bits (32-bit) at flat index f (< 2^32):
// counter = (hi=0, lo=f); bits = word0 ^ word1.
__device__ __forceinline__
float jax_uniform_at(uint32_t k0, uint32_t k1, uint32_t f)
{
    uint32_t y0, y1;
    threefry2x32(k0, k1, 0u, f, y0, y1);
    uint32_t bits = y0 ^ y1;
    return __uint_as_float((bits >> 9) | 0x3F800000u) - 1.0f;
}

// ---------------------------------------------------------------------------
// Kernel 1: y = bias (broadcast over batch)
// ---------------------------------------------------------------------------
__global__ void init_out_kernel(float* __restrict__ y, const float* __restrict__ bias)
{
    int o = blockIdx.x * blockDim.x + threadIdx.x;
    if (o < BB * CDIM) y[o] = bias[o & (CDIM - 1)];
}

// ---------------------------------------------------------------------------
// Kernel 2: one CTA per (b, c) group
// ---------------------------------------------------------------------------
__global__ void __launch_bounds__(512, 3)
sparse_main_kernel(const float* __restrict__ x,
                   const float* __restrict__ means,
                   const float* __restrict__ sigmas,
                   const float* __restrict__ values,
                   float* __restrict__ y,
                   uint32_t kg0, uint32_t kg1, uint32_t kl0, uint32_t kl1)
{
    extern __shared__ char sm[];
    char* rows = sm;                                   // 512 rows x 136 B
    float* vno = (float*)(sm + ROWS_BYTES);            // [64] (16B aligned)
    float* mm0 = vno + KCOMP;
    float* mm1 = mm0 + KCOMP;
    float* qq0 = mm1 + KCOMP;                          // -0.5*log2(e)/(eps+sigma)
    float* qq1 = qq0 + KCOMP;

    const int grp = blockIdx.x;          // b*256 + c
    const int b   = grp >> 8;
    const int c   = grp & 255;
    const int tid = threadIdx.x;

    const float OME   = (float)(1.0 - 1e-6);
    const float NHL2E = -0.72134752044448170f; // -0.5 * log2(e)

    // ---- load component params ----
    if (tid < KCOMP) {
        int k = tid;
        size_t base = ((size_t)b * NTOK + (size_t)c * KCOMP + k);
        mm0[k] = means[base * 2 + 0];
        mm1[k] = means[base * 2 + 1];
        qq0[k] = NHL2E / (1e-6f + sigmas[base * 2 + 0]);
        qq1[k] = NHL2E / (1e-6f + sigmas[base * 2 + 1]);
    }
    __syncthreads();

    // ---- generate 512 integer points; store into row padding ----
    {
        int k = tid >> 3;
        int j = tid & 7;
        float m0 = mm0[k], m1 = mm1[k];
        float r0, r1;
        if (j < 4) {
            // combos from itertools.product([True,False],2): True -> floor
            r0 = (j < 2)        ? floorf(m0) : ceilf(m0);
            r1 = ((j & 1) == 0) ? floorf(m1) : ceilf(m1);
        } else {
            int g = j & 1;
            uint32_t fbase = (uint32_t)(((grp * KCOMP + k) * 2 + g) * 2);
            if (j < 6) {
                float u0 = jax_uniform_at(kg0, kg1, fbase + 0);
                float u1 = jax_uniform_at(kg0, kg1, fbase + 1);
                r0 = floorf((u0 * OME) * 8192.0f);
                r1 = floorf((u1 * OME) * 8192.0f);
            } else {
                float u0 = jax_uniform_at(kl0, kl1, fbase + 0);
                float u1 = jax_uniform_at(kl0, kl1, fbase + 1);
                float mr0 = rintf(m0), mr1 = rintf(m1);
                float lo0 = mr0 - 8.0f;
                if (lo0 < 0.0f) lo0 = 0.0f;
                if (mr0 + 8.0f > 8192.0f) lo0 = 8176.0f;
                float lo1 = mr1 - 8.0f;
                if (lo1 < 0.0f) lo1 = 0.0f;
                if (mr1 + 8.0f > 8192.0f) lo1 = 8176.0f;
                r0 = floorf((u0 * OME) * 16.0f + lo0);
                r1 = floorf((u1 * OME) * 16.0f + lo1);
            }
        }
        r0 = fminf(fmaxf(r0, 0.0f), 8191.0f);
        r1 = fminf(fmaxf(r1, 0.0f), 8191.0f);
        *(float2*)(rows + tid * ROW_BYTES + 128) = make_float2(r0, r1);
    }
    __syncthreads();

    // ---- density pass: thread = (k-pair p, io); i = io + 16s ----
    {
        int p  = tid >> 4;       // 0..31 -> k = 2p, 2p+1
        int io = tid & 15;
        int ka = 2 * p, kb = ka + 1;
        float ma0 = mm0[ka], ma1 = mm1[ka], qa0 = qq0[ka], qa1 = qq1[ka];
        float mb0 = mm0[kb], mb1 = mm1[kb], qb0 = qq0[kb], qb1 = qq1[kb];
        float acc0 = 0.0f, acc1 = 0.0f;
        char* row = rows + io * ROW_BYTES;
#pragma unroll 8
        for (int s = 0; s < 32; s++) {
            float2 pt = *(float2*)(row + 128);
            float da0 = pt.x - ma0, da1 = pt.y - ma1;
            float ta  = fmaf(da1 * da1, qa1, da0 * da0 * qa0);
            float ea  = fmaxf(exp2f(ta), 1e-6f);
            float db0 = pt.x - mb0, db1 = pt.y - mb1;
            float tb  = fmaf(db1 * db1, qb1, db0 * db0 * qb0);
            float eb  = fmaxf(exp2f(tb), 1e-6f);
            acc0 += ea;
            acc1 += eb;
            *(__half2*)(row + p * 4) =
                __floats2half2_rn(ea * 1024.0f, eb * 1024.0f);
            row += 16 * ROW_BYTES;
        }
        // reduce over the 16 io lanes (lane = (p&1)*16 + io)
        acc0 += __shfl_down_sync(0xFFFFFFFFu, acc0, 8, 16);
        acc1 += __shfl_down_sync(0xFFFFFFFFu, acc1, 8, 16);
        acc0 += __shfl_down_sync(0xFFFFFFFFu, acc0, 4, 16);
        acc1 += __shfl_down_sync(0xFFFFFFFFu, acc1, 4, 16);
        acc0 += __shfl_down_sync(0xFFFFFFFFu, acc0, 2, 16);
        acc1 += __shfl_down_sync(0xFFFFFFFFu, acc1, 2, 16);
        acc0 += __shfl_down_sync(0xFFFFFFFFu, acc0, 1, 16);
        acc1 += __shfl_down_sync(0xFFFFFFFFu, acc1, 1, 16);
        if (io == 0) {
            size_t vb = (size_t)b * NTOK + (size_t)c * KCOMP;
            vno[ka] = (values[vb + ka] / acc0) * (1.0f / 1024.0f);
            vno[kb] = (values[vb + kb] / acc1) * (1.0f / 1024.0f);
        }
    }
    __syncthreads();

    // ---- weights + gather + scatter (thread = point i) ----
    {
        char* row = rows + tid * ROW_BYTES;
        float w = 0.0f;
#pragma unroll
        for (int k4 = 0; k4 < KCOMP; k4 += 4) {
            uint2  d = *(uint2*)(row + k4 * 2);       // 4 halfs
            float4 v = *(float4*)(vno + k4);          // broadcast
            __half2 h01 = *(__half2*)&d.x;
            __half2 h23 = *(__half2*)&d.y;
            w = fmaf(__low2float(h01),  v.x, w);
            w = fmaf(__high2float(h01), v.y, w);
            w = fmaf(__low2float(h23),  v.z, w);
            w = fmaf(__high2float(h23), v.w, w);
        }
        float2 pt = *(float2*)(row + 128);
        int i0 = (int)pt.x;
        int i1 = (int)pt.y;
        float g = x[(size_t)b * CDIM + i1];
        atomicAdd(&y[(size_t)b * CDIM + i0], w * g);
    }
}

// ---------------------------------------------------------------------------
// Launch
// ---------------------------------------------------------------------------
extern "C" void kernel_launch(void* const* d_in, const int* in_sizes, int n_in,
                              void* d_out, int out_size)
{
    const float* x      = (const float*)d_in[0];
    const float* means  = (const float*)d_in[1];
    const float* sigmas = (const float*)d_in[2];
    const float* values = (const float*)d_in[3];
    const float* bias   = (const float*)d_in[4];
    float* y = (float*)d_out;

    // jax_threefry_partitionable split (fold-like)
    uint32_t kg0, kg1, kl0, kl1;
    threefry2x32(0u, 42u, 0u, 0u, kg0, kg1);
    threefry2x32(0u, 42u, 0u, 1u, kl0, kl1);

    init_out_kernel<<<(BB * CDIM + 255) / 256, 256>>>(y, bias);

    cudaFuncSetAttribute(sparse_main_kernel,
                         cudaFuncAttributeMaxDynamicSharedMemorySize, SMEM_BYTES);
    sparse_main_kernel<<<BB * CGRP, 512, SMEM_BYTES>>>(
        x, means, sigmas, values, y, kg0, kg1, kl0, kl1);
}

// round 6
// speedup vs baseline: 1.7770x; 1.0837x over previous
#include <cuda_runtime.h>
#include <cuda_fp16.h>
#include <cstdint>

// Problem constants
#define BB    8
#define NTOK  16384
#define KCOMP 64
#define CGRP  256       // N / K
#define CDIM  8192      // C_OUT == C_IN
#define IPTS  512       // points per group = K * 8
#define NGRP  (BB * CGRP)       // 2048
#define HK    32        // k's per CTA (K split in 2)

// Row: 32 halfs (dens for this CTA's k-half, scaled e*1024) + float2 point
#define PITCH_W 18      // words per row (16 dens words + 2 point words)

// Global scratch: all integer points, shared by both k-half CTAs
__device__ float2 g_pts[NGRP * IPTS];   // 8 MB

// ---------------------------------------------------------------------------
// threefry2x32 (20 rounds)
// ---------------------------------------------------------------------------
__host__ __device__ __forceinline__
void threefry2x32(uint32_t k0, uint32_t k1, uint32_t x0, uint32_t x1,
                  uint32_t& y0, uint32_t& y1)
{
    uint32_t ks2 = k0 ^ k1 ^ 0x1BD11BDAu;
#define TF_RND(r) { x0 += x1; x1 = (x1 << (r)) | (x1 >> (32 - (r))); x1 ^= x0; }
    x0 += k0; x1 += k1;
    TF_RND(13) TF_RND(15) TF_RND(26) TF_RND(6)
    x0 += k1;  x1 += ks2 + 1u;
    TF_RND(17) TF_RND(29) TF_RND(16) TF_RND(24)
    x0 += ks2; x1 += k0 + 2u;
    TF_RND(13) TF_RND(15) TF_RND(26) TF_RND(6)
    x0 += k0;  x1 += k1 + 3u;
    TF_RND(17) TF_RND(29) TF_RND(16) TF_RND(24)
    x0 += k1;  x1 += ks2 + 4u;
    TF_RND(13) TF_RND(15) TF_RND(26) TF_RND(6)
    x0 += ks2; x1 += k0 + 5u;
#undef TF_RND
    y0 = x0; y1 = x1;
}

// jax partitionable random_bits: counter (0, f); bits = w0 ^ w1
__device__ __forceinline__
float jax_uniform_at(uint32_t k0, uint32_t k1, uint32_t f)
{
    uint32_t y0, y1;
    threefry2x32(k0, k1, 0u, f, y0, y1);
    uint32_t bits = y0 ^ y1;
    return __uint_as_float((bits >> 9) | 0x3F800000u) - 1.0f;
}

// ---------------------------------------------------------------------------
// Kernel 0: y = bias
// ---------------------------------------------------------------------------
__global__ void init_out_kernel(float* __restrict__ y, const float* __restrict__ bias)
{
    int o = blockIdx.x * blockDim.x + threadIdx.x;
    if (o < BB * CDIM) y[o] = bias[o & (CDIM - 1)];
}

// ---------------------------------------------------------------------------
// Kernel 1: generate all points. One CTA per group; one threefry per thread.
// ---------------------------------------------------------------------------
__global__ void __launch_bounds__(512)
points_kernel(const float* __restrict__ means,
              uint32_t kg0, uint32_t kg1, uint32_t kl0, uint32_t kl1)
{
    __shared__ float us[512];   // uniforms * (1-eps): [0..255]=kg, [256..511]=kl
    const int grp = blockIdx.x;
    const int tid = threadIdx.x;
    const float OME = (float)(1.0 - 1e-6);

    // phase 1: exactly one uniform per thread (balanced warps)
    {
        uint32_t s  = (uint32_t)tid >> 8;
        uint32_t f  = (uint32_t)grp * 256u + ((uint32_t)tid & 255u);
        uint32_t a0 = s ? kl0 : kg0;
        uint32_t a1 = s ? kl1 : kg1;
        us[tid] = jax_uniform_at(a0, a1, f) * OME;
    }
    __syncthreads();

    // phase 2: one point per thread
    const int k = tid >> 3;
    const int j = tid & 7;
    size_t mbase = ((size_t)grp * KCOMP + k) * 2;
    float m0 = means[mbase + 0];
    float m1 = means[mbase + 1];
    float r0, r1;
    if (j < 4) {
        r0 = (j < 2)        ? floorf(m0) : ceilf(m0);
        r1 = ((j & 1) == 0) ? floorf(m1) : ceilf(m1);
    } else {
        int base = (((j >> 1) & 1) << 8) + 4 * k + ((j & 1) << 1);
        float u0 = us[base];
        float u1 = us[base + 1];
        if (j < 6) {
            r0 = floorf(u0 * 8192.0f);
            r1 = floorf(u1 * 8192.0f);
        } else {
            float mr0 = rintf(m0), mr1 = rintf(m1);
            float lo0 = mr0 - 8.0f;
            if (lo0 < 0.0f) lo0 = 0.0f;
            if (mr0 + 8.0f > 8192.0f) lo0 = 8176.0f;
            float lo1 = mr1 - 8.0f;
            if (lo1 < 0.0f) lo1 = 0.0f;
            if (mr1 + 8.0f > 8192.0f) lo1 = 8176.0f;
            r0 = floorf(u0 * 16.0f + lo0);
            r1 = floorf(u1 * 16.0f + lo1);
        }
    }
    r0 = fminf(fmaxf(r0, 0.0f), 8191.0f);
    r1 = fminf(fmaxf(r1, 0.0f), 8191.0f);
    g_pts[grp * IPTS + tid] = make_float2(r0, r1);
}

// ---------------------------------------------------------------------------
// Kernel 2: main. One CTA per (group, k-half). 4 CTAs/SM (36.7 KB smem).
// ---------------------------------------------------------------------------
__global__ void __launch_bounds__(512, 4)
sparse_main_kernel(const float* __restrict__ x,
                   const float* __restrict__ means,
                   const float* __restrict__ sigmas,
                   const float* __restrict__ values,
                   float* __restrict__ y)
{
    __shared__ __align__(16) float vno[HK];
    __shared__ float mm0[HK], mm1[HK], qq0[HK], qq1[HK];
    __shared__ uint32_t rows[IPTS * PITCH_W];   // 36864 B

    const int bx   = blockIdx.x;
    const int grp  = bx >> 1;            // consecutive pair shares the group
    const int koff = (bx & 1) * HK;
    const int b    = grp >> 8;
    const int tid  = threadIdx.x;

    const float NHL2E = -0.72134752044448170f;  // -0.5*log2(e)
    const float TEN   = 10.0f;                  // folds the *1024 fp16 scale

    // ---- params for this CTA's 32 components ----
    if (tid < HK) {
        size_t base = ((size_t)grp * KCOMP + koff + tid);
        mm0[tid] = means[base * 2 + 0];
        mm1[tid] = means[base * 2 + 1];
        qq0[tid] = NHL2E / (1e-6f + sigmas[base * 2 + 0]);
        qq1[tid] = NHL2E / (1e-6f + sigmas[base * 2 + 1]);
    }
    // ---- points into row tail ----
    {
        float2 pt = g_pts[grp * IPTS + tid];
        *(float2*)(rows + tid * PITCH_W + 16) = pt;
    }
    __syncthreads();

    // ---- density: warp = 2 components (ka, kb); lane = io over 32 points ----
    {
        const int p  = tid >> 5;         // 0..15
        const int io = tid & 31;
        const int ka = 2 * p, kb = ka + 1;
        const float ma0 = mm0[ka], ma1 = mm1[ka], qa0 = qq0[ka], qa1 = qq1[ka];
        const float mb0 = mm0[kb], mb1 = mm1[kb], qb0 = qq0[kb], qb1 = qq1[kb];
        float acc0 = 0.0f, acc1 = 0.0f;
        uint32_t* row = rows + io * PITCH_W;
#pragma unroll
        for (int s = 0; s < 16; s++) {
            float2 pt = *(float2*)(row + 16);
            float da0 = pt.x - ma0, da1 = pt.y - ma1;
            float ta  = fmaf(da0 * da0, qa0, TEN);
            ta        = fmaf(da1 * da1, qa1, ta);
            float ea  = fmaxf(exp2f(ta), 1.024e-3f);   // = 1024*max(e,1e-6)
            float db0 = pt.x - mb0, db1 = pt.y - mb1;
            float tb  = fmaf(db0 * db0, qb0, TEN);
            tb        = fmaf(db1 * db1, qb1, tb);
            float eb  = fmaxf(exp2f(tb), 1.024e-3f);
            acc0 += ea;
            acc1 += eb;
            *(__half2*)(row + p) = __floats2half2_rn(ea, eb);
            row += 32 * PITCH_W;
        }
#pragma unroll
        for (int off = 16; off > 0; off >>= 1) {
            acc0 += __shfl_down_sync(0xFFFFFFFFu, acc0, off);
            acc1 += __shfl_down_sync(0xFFFFFFFFu, acc1, off);
        }
        if (io == 0) {
            size_t vb = (size_t)grp * KCOMP + koff;
            vno[ka] = values[vb + ka] / acc0;   // 1024-scales cancel exactly
            vno[kb] = values[vb + kb] / acc1;
        }
    }
    __syncthreads();

    // ---- partial weights + gather + scatter (thread = point) ----
    {
        uint32_t* row = rows + tid * PITCH_W;
        float w = 0.0f;
#pragma unroll
        for (int c4 = 0; c4 < 8; c4++) {
            uint2  d = *(uint2*)(row + c4 * 2);     // 4 halfs
            float4 v = *(float4*)(vno + c4 * 4);    // broadcast
            __half2 h01 = *(__half2*)&d.x;
            __half2 h23 = *(__half2*)&d.y;
            w = fmaf(__low2float(h01),  v.x, w);
            w = fmaf(__high2float(h01), v.y, w);
            w = fmaf(__low2float(h23),  v.z, w);
            w = fmaf(__high2float(h23), v.w, w);
        }
        float2 pt = *(float2*)(row + 16);
        int i0 = (int)pt.x;
        int i1 = (int)pt.y;
        float g = x[(size_t)b * CDIM + i1];
        atomicAdd(&y[(size_t)b * CDIM + i0], w * g);
    }
}

// ---------------------------------------------------------------------------
// Launch
// ---------------------------------------------------------------------------
extern "C" void kernel_launch(void* const* d_in, const int* in_sizes, int n_in,
                              void* d_out, int out_size)
{
    const float* x      = (const float*)d_in[0];
    const float* means  = (const float*)d_in[1];
    const float* sigmas = (const float*)d_in[2];
    const float* values = (const float*)d_in[3];
    const float* bias   = (const float*)d_in[4];
    float* y = (float*)d_out;

    // jax_threefry_partitionable split of key(42)
    uint32_t kg0, kg1, kl0, kl1;
    threefry2x32(0u, 42u, 0u, 0u, kg0, kg1);
    threefry2x32(0u, 42u, 0u, 1u, kl0, kl1);

    init_out_kernel<<<(BB * CDIM + 255) / 256, 256>>>(y, bias);
    points_kernel<<<NGRP, 512>>>(means, kg0, kg1, kl0, kl1);
    sparse_main_kernel<<<NGRP * 2, 512>>>(x, means, sigmas, values, y);
}